// round 3
// baseline (speedup 1.0000x reference)
#include <cuda_runtime.h>
#include <cstdint>

// Problem constants
#define BB   8
#define CIN  64
#define COUT 128
#define HH   224
#define WW   224
#define PTCH 16
#define GG   14     // 14x14 patch grid
#define NP   196

typedef unsigned long long u64;

// Scratch (device globals — no allocations allowed)
__device__ u64 g_sx[BB * HH * WW];   // packed sign(x), bit c = sign of channel c
__device__ u64 g_m [BB * HH * WW];   // nonzero mask of bsa
__device__ u64 g_s [BB * HH * WW];   // sign bit of bsa (1 = negative)
__device__ u64 g_pw[NP * 9];         // packed sign(patch_filters) per (patch, tap)
__device__ u64 g_ow[COUT * 9];       // packed sign(output_filters) per (o, tap)

// Output-conv weights in constant memory -> warp-uniform ULDC loads (uniform
// datapath, no LSU/MIO pressure inside the hot loop).
__constant__ u64 c_ow[COUT * 9];

// ---------------------------------------------------------------------------
// Kernel 0: pack sign bits of x: [B, C=64, H, W] -> u64 per (b, y, x)
// 4 pixels per thread, float4 loads for full HBM bandwidth.
// ---------------------------------------------------------------------------
__global__ void __launch_bounds__(256) pack_x_kernel(const float* __restrict__ x) {
    int q = blockIdx.x * blockDim.x + threadIdx.x;       // quad index
    const int NQ = BB * HH * WW / 4;
    if (q >= NQ) return;
    int pix = q * 4;
    int b   = pix / (HH * WW);
    int rem = pix - b * (HH * WW);
    const float4* xp = (const float4*)(x + (size_t)b * CIN * HH * WW + rem);
    u64 w0 = 0, w1 = 0, w2 = 0, w3 = 0;
#pragma unroll
    for (int c = 0; c < CIN; c++) {
        float4 v = xp[(size_t)c * (HH * WW / 4)];
        w0 |= (u64)(__float_as_uint(v.x) >> 31) << c;
        w1 |= (u64)(__float_as_uint(v.y) >> 31) << c;
        w2 |= (u64)(__float_as_uint(v.z) >> 31) << c;
        w3 |= (u64)(__float_as_uint(v.w) >> 31) << c;
    }
    g_sx[pix + 0] = w0;
    g_sx[pix + 1] = w1;
    g_sx[pix + 2] = w2;
    g_sx[pix + 3] = w3;
}

// ---------------------------------------------------------------------------
// Kernel 0b: pack filter sign bits
// ---------------------------------------------------------------------------
__global__ void pack_filters_kernel(const float* __restrict__ pf,
                                    const float* __restrict__ of) {
    int i = blockIdx.x * blockDim.x + threadIdx.x;
    if (i < NP * 9) {
        int p = i / 9, t = i - p * 9;
        u64 w = 0;
#pragma unroll
        for (int c = 0; c < CIN; c++) {
            unsigned sb = __float_as_uint(pf[((size_t)c * NP + p) * 9 + t]) >> 31;
            w |= (u64)sb << c;
        }
        g_pw[i] = w;
    } else if (i < NP * 9 + COUT * 9) {
        int j = i - NP * 9;
        int o = j / 9, t = j - o * 9;
        u64 w = 0;
#pragma unroll
        for (int c = 0; c < CIN; c++) {
            unsigned sb = __float_as_uint(of[((size_t)o * CIN + c) * 9 + t]) >> 31;
            w |= (u64)sb << c;
        }
        g_ow[j] = w;
    }
}

// ---------------------------------------------------------------------------
// Kernel 1: per-patch depthwise binary 3x3 conv (zero pad inside 16x16 patch),
// then ternary quantize: sa = n_valid - 2*mismatch; emit m (sa!=0), s (sa<0).
// ---------------------------------------------------------------------------
__global__ void __launch_bounds__(256) stage1_kernel() {
    __shared__ u64 tile[PTCH][PTCH];
    __shared__ u64 pw9[9];

    const int gx = blockIdx.x, gy = blockIdx.y, b = blockIdx.z;
    const int j = threadIdx.x, i = threadIdx.y;
    const int tid = i * PTCH + j;
    const int patch = gy * GG + gx;

    const int y = gy * PTCH + i;
    const int x = gx * PTCH + j;
    const int pixbase = b * HH * WW;

    tile[i][j] = g_sx[pixbase + y * WW + x];
    if (tid < 9) pw9[tid] = g_pw[patch * 9 + tid];
    __syncthreads();

    u64 c0 = 0, c1 = 0, c2 = 0, c3 = 0;
#pragma unroll
    for (int di = 0; di < 3; di++) {
#pragma unroll
        for (int dj = 0; dj < 3; dj++) {
            int li = i + di - 1, lj = j + dj - 1;
            if (li >= 0 && li < PTCH && lj >= 0 && lj < PTCH) {
                u64 d = tile[li][lj] ^ pw9[di * 3 + dj];
                u64 carry = d, u;
                u = c0 & carry; c0 ^= carry; carry = u;
                u = c1 & carry; c1 ^= carry; carry = u;
                u = c2 & carry; c2 ^= carry; carry = u;
                c3 ^= carry;
            }
        }
    }

    const int ni = (i == 0 || i == PTCH - 1) ? 2 : 3;
    const int nj = (j == 0 || j == PTCH - 1) ? 2 : 3;
    const int n  = ni * nj;

    u64 m, s;
    if (n == 9) {
        m = ~0ULL;
        s = c3 | (c2 & (c1 | c0));
    } else if (n == 6) {
        m = ~(c0 & c1 & ~c2);
        s = c2;
    } else { // n == 4
        m = ~(c1 & ~c0 & ~c2);
        s = (c0 & c1) | c2;
    }

    g_m[pixbase + y * WW + x] = m;
    g_s[pixbase + y * WW + x] = s;
}

// ---------------------------------------------------------------------------
// Kernel 2: final binary 3x3 conv, 64 -> 128 channels, image-level zero pad.
// out[b,o,y,x] = sum_t popc(m_t) - 2 * sum_t popc(m_t & (s_t ^ w_{o,t}))
//
// Block = 16x8 pixel tile x 2 output-channel halves (256 threads).
// Each thread: 1 pixel, 64 output channels. Weights come from __constant__
// (warp-uniform -> ULDC on the uniform datapath).
// ---------------------------------------------------------------------------
#define TX 16
#define TY 8

__global__ void __launch_bounds__(256, 4) stage2_kernel(float* __restrict__ out) {
    __shared__ u64 smM[TY + 2][TX + 2];
    __shared__ u64 smS[TY + 2][TX + 2];

    const int b  = blockIdx.z;
    const int x0 = blockIdx.x * TX;
    const int y0 = blockIdx.y * TY;
    const int tx = threadIdx.x, ty = threadIdx.y, tz = threadIdx.z;
    const int tid = (tz * TY + ty) * TX + tx;

    // Load halo tile of (m, s): 18*10 = 180 entries, 256 threads.
    if (tid < (TY + 2) * (TX + 2)) {
        int ly = tid / (TX + 2), lx = tid - ly * (TX + 2);
        int gy = y0 - 1 + ly, gx = x0 - 1 + lx;
        u64 m = 0, s = 0;
        if (gy >= 0 && gy < HH && gx >= 0 && gx < WW) {
            int p = b * HH * WW + gy * WW + gx;
            m = g_m[p];
            s = g_s[p];
        }
        smM[ly][lx] = m;
        smS[ly][lx] = s;
    }
    __syncthreads();

    // This pixel's 9 neighbor words in registers.
    u64 mm[9], ss[9];
#pragma unroll
    for (int di = 0; di < 3; di++)
#pragma unroll
        for (int dj = 0; dj < 3; dj++) {
            mm[di * 3 + dj] = smM[ty + di][tx + dj];
            ss[di * 3 + dj] = smS[ty + di][tx + dj];
        }

    int base = 0;
#pragma unroll
    for (int t = 0; t < 9; t++) base += __popcll(mm[t]);

    const int o0 = tz * (COUT / 2);
    float* op = out + ((size_t)b * COUT + o0) * HH * WW
                    + (size_t)(y0 + ty) * WW + (x0 + tx);

#pragma unroll 8
    for (int o = 0; o < COUT / 2; o++) {
        int acc = 0;
#pragma unroll
        for (int t = 0; t < 9; t++)
            acc += __popcll(mm[t] & (ss[t] ^ c_ow[(o0 + o) * 9 + t]));
        op[(size_t)o * HH * WW] = (float)(base - 2 * acc);
    }
}

// ---------------------------------------------------------------------------
// Launch
// ---------------------------------------------------------------------------
extern "C" void kernel_launch(void* const* d_in, const int* in_sizes, int n_in,
                              void* d_out, int out_size) {
    const float* x  = (const float*)d_in[0];
    const float* pf = (const float*)d_in[2];
    const float* of = (const float*)d_in[3];
    float* out = (float*)d_out;

    const int nquads = BB * HH * WW / 4;
    pack_x_kernel<<<(nquads + 255) / 256, 256>>>(x);

    const int nw = NP * 9 + COUT * 9;
    pack_filters_kernel<<<(nw + 255) / 256, 256>>>(pf, of);

    // Copy packed output-conv weights into constant memory (D2D, capturable).
    void* gow_ptr = nullptr;
    cudaGetSymbolAddress(&gow_ptr, g_ow);
    cudaMemcpyToSymbolAsync(c_ow, gow_ptr, sizeof(u64) * COUT * 9, 0,
                            cudaMemcpyDeviceToDevice, 0);

    stage1_kernel<<<dim3(GG, GG, BB), dim3(PTCH, PTCH)>>>();

    stage2_kernel<<<dim3(WW / TX, HH / TY, BB), dim3(TX, TY, 2)>>>(out);
}

// round 4
// speedup vs baseline: 1.4840x; 1.4840x over previous
#include <cuda_runtime.h>
#include <cstdint>

// Problem constants
#define BB   8
#define CIN  64
#define COUT 128
#define HH   224
#define WW   224
#define HW   (HH * WW)
#define PTCH 16
#define GG   14     // 14x14 patch grid
#define NP   196

typedef unsigned long long u64;
typedef unsigned int u32;

// ---------------------------------------------------------------------------
// Scratch (device globals — no allocations allowed)
// ---------------------------------------------------------------------------
__device__ u64 g_sx[BB * HW];                          // packed sign(x)
__device__ u64 g_pw[NP * 9];                           // packed sign(patch_filters)
__device__ __align__(16) int8_t g_bsa[(size_t)BB * HW * CIN];  // ternary bsa, channels-last

#define WA_STRIDE 592                                  // 576 + pad (bank-conflict-free)
__device__ __align__(16) int8_t g_wA[COUT * WA_STRIDE];  // int8 weights, row o, k = t*64+h*32+kl

// ---------------------------------------------------------------------------
// Kernel 0: pack sign bits of x (4 pixels/thread, float4 loads)
// ---------------------------------------------------------------------------
__global__ void __launch_bounds__(256) pack_x_kernel(const float* __restrict__ x) {
    int q = blockIdx.x * blockDim.x + threadIdx.x;
    const int NQ = BB * HW / 4;
    if (q >= NQ) return;
    int pix = q * 4;
    int b   = pix / HW;
    int rem = pix - b * HW;
    const float4* xp = (const float4*)(x + (size_t)b * CIN * HW + rem);
    u64 w0 = 0, w1 = 0, w2 = 0, w3 = 0;
#pragma unroll
    for (int c = 0; c < CIN; c++) {
        float4 v = xp[(size_t)c * (HW / 4)];
        w0 |= (u64)(__float_as_uint(v.x) >> 31) << c;
        w1 |= (u64)(__float_as_uint(v.y) >> 31) << c;
        w2 |= (u64)(__float_as_uint(v.z) >> 31) << c;
        w3 |= (u64)(__float_as_uint(v.w) >> 31) << c;
    }
    g_sx[pix + 0] = w0;
    g_sx[pix + 1] = w1;
    g_sx[pix + 2] = w2;
    g_sx[pix + 3] = w3;
}

// ---------------------------------------------------------------------------
// Kernel 0b: pack patch-filter sign bits (for stage1)
// ---------------------------------------------------------------------------
__global__ void pack_pf_kernel(const float* __restrict__ pf) {
    int i = blockIdx.x * blockDim.x + threadIdx.x;
    if (i >= NP * 9) return;
    int p = i / 9, t = i - p * 9;
    u64 w = 0;
#pragma unroll
    for (int c = 0; c < CIN; c++) {
        unsigned sb = __float_as_uint(pf[((size_t)c * NP + p) * 9 + t]) >> 31;
        w |= (u64)sb << c;
    }
    g_pw[i] = w;
}

// ---------------------------------------------------------------------------
// Kernel 0c: pack output-conv weights as int8 rows wA[o][kg], kg = t*64 + c.
// ---------------------------------------------------------------------------
__global__ void pack_wA_kernel(const float* __restrict__ of) {
    int idx = blockIdx.x * blockDim.x + threadIdx.x;
    if (idx >= COUT * WA_STRIDE) return;
    int o = idx / WA_STRIDE, kg = idx - o * WA_STRIDE;
    int8_t v = 0;
    if (kg < 576) {
        int t = kg >> 6, c = kg & 63;
        unsigned sb = __float_as_uint(of[((size_t)o * CIN + c) * 9 + t]) >> 31;
        v = sb ? (int8_t)-1 : (int8_t)1;
    }
    g_wA[idx] = v;
}

// ---------------------------------------------------------------------------
// Kernel 1: per-patch depthwise binary 3x3 conv -> ternary bsa as int8.
// ---------------------------------------------------------------------------
__global__ void __launch_bounds__(256) stage1_kernel() {
    __shared__ u64 tile[PTCH][PTCH];
    __shared__ u64 pw9[9];

    const int gx = blockIdx.x, gy = blockIdx.y, b = blockIdx.z;
    const int j = threadIdx.x, i = threadIdx.y;
    const int tid = i * PTCH + j;
    const int patch = gy * GG + gx;

    const int y = gy * PTCH + i;
    const int x = gx * PTCH + j;
    const int pixbase = b * HW;

    tile[i][j] = g_sx[pixbase + y * WW + x];
    if (tid < 9) pw9[tid] = g_pw[patch * 9 + tid];
    __syncthreads();

    u64 c0 = 0, c1 = 0, c2 = 0, c3 = 0;
#pragma unroll
    for (int di = 0; di < 3; di++) {
#pragma unroll
        for (int dj = 0; dj < 3; dj++) {
            int li = i + di - 1, lj = j + dj - 1;
            if (li >= 0 && li < PTCH && lj >= 0 && lj < PTCH) {
                u64 d = tile[li][lj] ^ pw9[di * 3 + dj];
                u64 carry = d, u;
                u = c0 & carry; c0 ^= carry; carry = u;
                u = c1 & carry; c1 ^= carry; carry = u;
                u = c2 & carry; c2 ^= carry; carry = u;
                c3 ^= carry;
            }
        }
    }

    const int ni = (i == 0 || i == PTCH - 1) ? 2 : 3;
    const int nj = (j == 0 || j == PTCH - 1) ? 2 : 3;
    const int n  = ni * nj;

    u64 m, s;
    if (n == 9) {
        m = ~0ULL;
        s = c3 | (c2 & (c1 | c0));
    } else if (n == 6) {
        m = ~(c0 & c1 & ~c2);
        s = c2;
    } else { // n == 4
        m = ~(c1 & ~c0 & ~c2);
        s = (c0 & c1) | c2;
    }

    // Emit ternary int8: m ? (s ? -1 : +1) : 0, channels-last.
    u32 w32[16];
#pragma unroll
    for (int wi = 0; wi < 16; wi++) {
        u32 v = 0;
#pragma unroll
        for (int bi = 0; bi < 4; bi++) {
            int c = wi * 4 + bi;
            u32 mb = (u32)((m >> c) & 1ULL);
            u32 sb = (u32)((s >> c) & 1ULL);
            u32 byte = mb ? (sb ? 0xFFu : 0x01u) : 0u;
            v |= byte << (bi * 8);
        }
        w32[wi] = v;
    }
    uint4* dst = (uint4*)(g_bsa + ((size_t)(pixbase + y * WW + x)) * CIN);
    dst[0] = make_uint4(w32[0],  w32[1],  w32[2],  w32[3]);
    dst[1] = make_uint4(w32[4],  w32[5],  w32[6],  w32[7]);
    dst[2] = make_uint4(w32[8],  w32[9],  w32[10], w32[11]);
    dst[3] = make_uint4(w32[12], w32[13], w32[14], w32[15]);
}

// ---------------------------------------------------------------------------
// Kernel 2: final conv as int8 implicit GEMM via mma.sync (IMMA).
//   M = COUT (128 = 8 m16), N = 256 pixels (16x16 tile = 32 n8), K = 576.
//   A = weights (row-major, smem), B = bsa halo (k-contiguous = col-major).
//   Block: 512 threads = 2 M-warps x 8 N-warps; warp tile 4 m16 x 4 n8.
// ---------------------------------------------------------------------------
#define HALO_STRIDE 80
#define SMEM_A_BYTES (COUT * WA_STRIDE)          // 75776
#define SMEM_HALO_BYTES (18 * 18 * HALO_STRIDE)  // 25920
#define SMEM_TOTAL (SMEM_A_BYTES + SMEM_HALO_BYTES)

__device__ __forceinline__ void mma_s8(int* d, const u32* a, const u32* b) {
    asm volatile(
        "mma.sync.aligned.m16n8k32.row.col.s32.s8.s8.s32 "
        "{%0,%1,%2,%3}, {%4,%5,%6,%7}, {%8,%9}, {%0,%1,%2,%3};\n"
        : "+r"(d[0]), "+r"(d[1]), "+r"(d[2]), "+r"(d[3])
        : "r"(a[0]), "r"(a[1]), "r"(a[2]), "r"(a[3]),
          "r"(b[0]), "r"(b[1]));
}

__global__ void __launch_bounds__(512, 1) stage2_kernel(float* __restrict__ out) {
    extern __shared__ char sm[];
    // [0, SMEM_A_BYTES): weights; [SMEM_A_BYTES, ...): bsa halo tile

    const int tid = threadIdx.x;
    const int b  = blockIdx.z;
    const int x0 = blockIdx.x * 16, y0 = blockIdx.y * 16;

    // Load weights into smem (L2-resident source)
    {
        const uint4* src = (const uint4*)g_wA;
        uint4* dst = (uint4*)sm;
        for (int i = tid; i < SMEM_A_BYTES / 16; i += 512) dst[i] = src[i];
    }
    // Load 18x18 pixel halo of bsa (64 B each), zero-padded at image edges
    if (tid < 324) {
        int hy = tid / 18, hx = tid - hy * 18;
        int gy = y0 - 1 + hy, gx = x0 - 1 + hx;
        uint4 v0 = make_uint4(0, 0, 0, 0), v1 = v0, v2 = v0, v3 = v0;
        if (gy >= 0 && gy < HH && gx >= 0 && gx < WW) {
            const uint4* s = (const uint4*)(g_bsa + ((size_t)((b * HH + gy) * WW + gx)) * CIN);
            v0 = s[0]; v1 = s[1]; v2 = s[2]; v3 = s[3];
        }
        uint4* d = (uint4*)(sm + SMEM_A_BYTES + (hy * 18 + hx) * HALO_STRIDE);
        d[0] = v0; d[1] = v1; d[2] = v2; d[3] = v3;
    }
    __syncthreads();

    const int warp = tid >> 5, lane = tid & 31;
    const int wm = warp & 1, wn = warp >> 1;       // 2 M-warps x 8 N-warps
    const int gid = lane >> 2, tig = lane & 3;
    const int o_base = wm * 64;

    // Per-mtile A offsets (bytes into sm). Row = o, 592B stride: conflict-free.
    int aoff[4];
#pragma unroll
    for (int i = 0; i < 4; i++)
        aoff[i] = (o_base + i * 16 + gid) * WA_STRIDE + tig * 4;

    // Per-ntile B offsets + output coords. n8 tile = 8 consecutive x, fixed y.
    int boff0[4], nty[4], ntx[4];
#pragma unroll
    for (int j = 0; j < 4; j++) {
        int ntg = wn * 4 + j;                       // 0..31
        int ty = ntg >> 1, tx8 = (ntg & 1) * 8;
        nty[j] = ty; ntx[j] = tx8;
        boff0[j] = SMEM_A_BYTES + (ty * 18 + tx8 + gid) * HALO_STRIDE + tig * 4;
    }

    int acc[4][4][4];
#pragma unroll
    for (int i = 0; i < 4; i++)
#pragma unroll
        for (int j = 0; j < 4; j++)
#pragma unroll
            for (int k = 0; k < 4; k++) acc[i][j][k] = 0;

    // K loop: ks = (tap t = ks>>1, half h = ks&1); kg = ks*32 + kl.
#pragma unroll
    for (int ks = 0; ks < 18; ks++) {
        const int t = ks >> 1, h = ks & 1;
        const int dy = t / 3, dx = t - dy * 3;
        const int bofs = (dy * 18 + dx) * HALO_STRIDE + h * 32;

        u32 a[4][4], bf[4][2];
#pragma unroll
        for (int i = 0; i < 4; i++) {
            int p = aoff[i] + ks * 32;
            a[i][0] = *(const u32*)(sm + p);
            a[i][1] = *(const u32*)(sm + p + 8 * WA_STRIDE);
            a[i][2] = *(const u32*)(sm + p + 16);
            a[i][3] = *(const u32*)(sm + p + 8 * WA_STRIDE + 16);
        }
#pragma unroll
        for (int j = 0; j < 4; j++) {
            int p = boff0[j] + bofs;
            bf[j][0] = *(const u32*)(sm + p);
            bf[j][1] = *(const u32*)(sm + p + 16);
        }
#pragma unroll
        for (int i = 0; i < 4; i++)
#pragma unroll
            for (int j = 0; j < 4; j++)
                mma_s8(acc[i][j], a[i], bf[j]);
    }

    // Epilogue: c frag row = o, col = pixel x -> coalesced 32B quad stores.
#pragma unroll
    for (int i = 0; i < 4; i++) {
        int o = o_base + i * 16 + gid;
#pragma unroll
        for (int j = 0; j < 4; j++) {
            int gy = y0 + nty[j];
            int gx = x0 + ntx[j] + tig * 2;
            size_t base0 = ((size_t)(b * COUT + o)) * HW + (size_t)gy * WW + gx;
            float2 v01 = make_float2((float)acc[i][j][0], (float)acc[i][j][1]);
            float2 v23 = make_float2((float)acc[i][j][2], (float)acc[i][j][3]);
            *(float2*)(out + base0) = v01;
            *(float2*)(out + base0 + (size_t)8 * HW) = v23;
        }
    }
}

// ---------------------------------------------------------------------------
// Launch
// ---------------------------------------------------------------------------
extern "C" void kernel_launch(void* const* d_in, const int* in_sizes, int n_in,
                              void* d_out, int out_size) {
    const float* x  = (const float*)d_in[0];
    const float* pf = (const float*)d_in[2];
    const float* of = (const float*)d_in[3];
    float* out = (float*)d_out;

    cudaFuncSetAttribute(stage2_kernel,
                         cudaFuncAttributeMaxDynamicSharedMemorySize, SMEM_TOTAL);

    const int nquads = BB * HW / 4;
    pack_x_kernel<<<(nquads + 255) / 256, 256>>>(x);

    pack_pf_kernel<<<(NP * 9 + 255) / 256, 256>>>(pf);
    pack_wA_kernel<<<(COUT * WA_STRIDE + 255) / 256, 256>>>(of);

    stage1_kernel<<<dim3(GG, GG, BB), dim3(PTCH, PTCH)>>>();

    stage2_kernel<<<dim3(WW / 16, HH / 16, BB), 512, SMEM_TOTAL>>>(out);
}